// round 10
// baseline (speedup 1.0000x reference)
#include <cuda_runtime.h>
#include <cuda_bf16.h>

// ChannelSelfAttention: B=4,H=512,W=256, C=2.
// s(w,u) = c0(w)*xa[u] + c1(w)*xb[u]  (bias terms cancel in softmax)
// A=Σe*xa, B=Σe*xb, D=Σe; V applied once per thread after the loop.
// 3/16 of exp2 pairs go to an fma-pipe deg-3 poly; rest on MUFU.
// Register diet: epilogue state reloaded post-loop, single acc streams,
// 5 packed constants, launch_bounds(256,6).

#define WIDTH 256

typedef unsigned long long u64;
typedef unsigned int u32;

__device__ __forceinline__ u64 f2_pack(float lo, float hi) {
    u64 r; asm("mov.b64 %0, {%1,%2};" : "=l"(r) : "f"(lo), "f"(hi)); return r;
}
__device__ __forceinline__ void f2_unpack(u64 v, float& lo, float& hi) {
    asm("mov.b64 {%0,%1}, %2;" : "=f"(lo), "=f"(hi) : "l"(v));
}
__device__ __forceinline__ void f2_unpack_u(u64 v, u32& lo, u32& hi) {
    asm("mov.b64 {%0,%1}, %2;" : "=r"(lo), "=r"(hi) : "l"(v));
}
__device__ __forceinline__ u64 f2_pack_u(u32 lo, u32 hi) {
    u64 r; asm("mov.b64 %0, {%1,%2};" : "=l"(r) : "r"(lo), "r"(hi)); return r;
}
__device__ __forceinline__ u64 f2_fma(u64 a, u64 b, u64 c) {
    u64 r; asm("fma.rn.f32x2 %0, %1, %2, %3;" : "=l"(r) : "l"(a), "l"(b), "l"(c)); return r;
}
__device__ __forceinline__ u64 f2_mul(u64 a, u64 b) {
    u64 r; asm("mul.rn.f32x2 %0, %1, %2;" : "=l"(r) : "l"(a), "l"(b)); return r;
}
__device__ __forceinline__ u64 f2_add(u64 a, u64 b) {
    u64 r; asm("add.rn.f32x2 %0, %1, %2;" : "=l"(r) : "l"(a), "l"(b)); return r;
}
__device__ __forceinline__ u64 f2_sub(u64 a, u64 b) {
    u64 r; asm("sub.rn.f32x2 %0, %1, %2;" : "=l"(r) : "l"(a), "l"(b)); return r;
}
__device__ __forceinline__ float fast_ex2(float s) {
    float e; asm("ex2.approx.ftz.f32 %0, %1;" : "=f"(e) : "f"(s)); return e;
}

// deg-3 poly exp2 on a packed pair, fma pipe + IMAD splice. |s| < ~126.
__device__ __forceinline__ u64 exp2_poly_f2(u64 s, u64 Kmagic, u64 Kone,
                                            u64 KC1, u64 KC2, u64 KC3) {
    u64 r = f2_add(s, Kmagic);              // round(s) in mantissa bits
    u64 f = f2_sub(s, f2_sub(r, Kmagic));   // f in [-0.5, 0.5]
    u64 p = f2_fma(f, KC3, KC2);
    p = f2_fma(f, p, KC1);
    p = f2_fma(f, p, Kone);
    u32 r0, r1, p0, p1;
    f2_unpack_u(r, r0, r1);
    f2_unpack_u(p, p0, p1);
    // bits(r)*2^23 ≡ (i<<23) mod 2^32 -> single IMAD splices the exponent
    return f2_pack_u(r0 * 8388608u + p0, r1 * 8388608u + p1);
}

__device__ __forceinline__ u64 exp2_mufu_f2(u64 s) {
    float s0, s1;
    f2_unpack(s, s0, s1);
    return f2_pack(fast_ex2(s0), fast_ex2(s1));
}

__global__ __launch_bounds__(WIDTH, 6) void channel_attn_kernel(
    const float* __restrict__ x1, const float* __restrict__ x2,
    const float* __restrict__ wq, const float* __restrict__ bq,
    const float* __restrict__ wk, const float* __restrict__ bk,
    const float* __restrict__ wv, const float* __restrict__ bv,
    float* __restrict__ out, int n_elem)
{
    __shared__ __align__(16) float sh[2 * WIDTH];   // [xa | xb]

    const int row  = blockIdx.x;
    const int w    = threadIdx.x;
    const int base = row * WIDTH;

    u64 c0p, c1p;
    {
        const float xa = x1[base + w];
        const float xb = x2[base + w];
        sh[w]         = xa;
        sh[WIDTH + w] = xb;

        const float q00 = __ldg(&wq[0]), q01 = __ldg(&wq[1]);
        const float q10 = __ldg(&wq[2]), q11 = __ldg(&wq[3]);
        const float k00 = __ldg(&wk[0]), k01 = __ldg(&wk[1]);
        const float k10 = __ldg(&wk[2]), k11 = __ldg(&wk[3]);
        const float bq0 = __ldg(&bq[0]), bq1 = __ldg(&bq[1]);
        // bk shifts every score of this thread equally -> cancels in softmax

        const float LOG2E = 1.4426950408889634f;
        const float a0 = fmaf(q00, xa, fmaf(q01, xb, bq0)) * LOG2E;
        const float a1 = fmaf(q10, xa, fmaf(q11, xb, bq1)) * LOG2E;
        const float c0 = fmaf(a0, k00, a1 * k10);
        const float c1 = fmaf(a0, k01, a1 * k11);
        c0p = f2_pack(c0, c0);
        c1p = f2_pack(c1, c1);
    }
    __syncthreads();

    // packed poly constants (deg-3 Taylor for exp2 on [-0.5, 0.5])
    const u64 Kmagic = f2_pack(12582912.0f, 12582912.0f);   // 1.5 * 2^23
    const u64 Kone   = f2_pack(1.0f, 1.0f);
    const u64 KC1    = f2_pack(0.6931471806f, 0.6931471806f);
    const u64 KC2    = f2_pack(0.2402265070f, 0.2402265070f);
    const u64 KC3    = f2_pack(0.0555041087f, 0.0555041087f);

    const unsigned sbase = (unsigned)__cvta_generic_to_shared(sh);

    u64 D = 0ull, A = 0ull, B = 0ull;

#pragma unroll 1
    for (int u0 = 0; u0 < WIDTH; u0 += 32) {
#pragma unroll
        for (int c = 0; c < 8; ++c) {        // 4 u per chunk, pairs (2c, 2c+1)
            const int off = (u0 + 4 * c) * 4;
            u64 xa01, xa23, xb01, xb23;
            asm("ld.shared.v2.b64 {%0,%1}, [%2];"
                : "=l"(xa01), "=l"(xa23) : "r"(sbase + off));
            asm("ld.shared.v2.b64 {%0,%1}, [%2];"
                : "=l"(xb01), "=l"(xb23) : "r"(sbase + off + WIDTH * 4));

            const u64 s01 = f2_fma(c0p, xa01, f2_mul(c1p, xb01));
            const u64 s23 = f2_fma(c0p, xa23, f2_mul(c1p, xb23));

            // poly on pair indices {2, 7, 12} of 16  (fraction 3/16)
            const bool poly01 = (2 * c == 2) || (2 * c == 12);
            const bool poly23 = (2 * c + 1 == 7);

            const u64 e01 = poly01
                ? exp2_poly_f2(s01, Kmagic, Kone, KC1, KC2, KC3)
                : exp2_mufu_f2(s01);
            const u64 e23 = poly23
                ? exp2_poly_f2(s23, Kmagic, Kone, KC1, KC2, KC3)
                : exp2_mufu_f2(s23);

            D = f2_add(D, f2_add(e01, e23));
            A = f2_fma(e01, xa01, f2_fma(e23, xa23, A));
            B = f2_fma(e01, xb01, f2_fma(e23, xb23, B));
        }
    }

    // ---- epilogue: everything reloaded here, not live through the loop ----
    float d0, d1, a0f, a1f, b0f, b1f;
    f2_unpack(D, d0, d1);
    f2_unpack(A, a0f, a1f);
    f2_unpack(B, b0f, b1f);
    const float Dv = d0 + d1;
    const float Av = a0f + a1f;
    const float Bv = b0f + b1f;

    const float v00 = __ldg(&wv[0]), v01 = __ldg(&wv[1]);
    const float v10 = __ldg(&wv[2]), v11 = __ldg(&wv[3]);
    const float bv0 = __ldg(&bv[0]), bv1 = __ldg(&bv[1]);
    const float xa = sh[w];
    const float xb = sh[WIDTH + w];

    const float inv = 1.0f / Dv;
    const float n0  = fmaf(v00, Av, fmaf(v01, Bv, bv0 * Dv));
    const float n1  = fmaf(v10, Av, fmaf(v11, Bv, bv1 * Dv));

    out[base + w]          = fmaf(n0, inv, xa);
    out[n_elem + base + w] = fmaf(n1, inv, xb);
}

extern "C" void kernel_launch(void* const* d_in, const int* in_sizes, int n_in,
                              void* d_out, int out_size)
{
    const float* x1 = (const float*)d_in[0];
    const float* x2 = (const float*)d_in[1];
    const float* wq = (const float*)d_in[2];
    const float* bq = (const float*)d_in[3];
    const float* wk = (const float*)d_in[4];
    const float* bk = (const float*)d_in[5];
    const float* wv = (const float*)d_in[6];
    const float* bv = (const float*)d_in[7];
    float* out = (float*)d_out;

    const int n_elem = in_sizes[0];        // B*H*W = 524288
    const int rows   = n_elem / WIDTH;     // B*H   = 2048

    channel_attn_kernel<<<rows, WIDTH>>>(x1, x2, wq, bq, wk, bk, wv, bv,
                                         out, n_elem);
}